// round 7
// baseline (speedup 1.0000x reference)
#include <cuda_runtime.h>
#include <cuda_fp16.h>
#include <cstdint>

#define BB 32
#define NN 1024
#define DD 512
#define LN_EPS 1e-5f

// ---------------- scratch (fragment-major fp16 tensors) ----------------
__device__ float  g_denom[BB * NN];
__device__ float  g_colsum[BB * NN];
__device__ float  g_x[BB * NN * DD];                       // fp32 activations (row-major)
__device__ __align__(16) __half g_adjF_h[(size_t)BB * NN * NN];   // adj frags
__device__ __align__(16) __half g_adjF_l[(size_t)BB * NN * NN];
__device__ __align__(16) __half g_xTF_h[(size_t)BB * DD * NN];    // x^T frags (B of gemm1)
__device__ __align__(16) __half g_xTF_l[(size_t)BB * DD * NN];
__device__ __align__(16) __half g_yF_h[(size_t)BB * NN * DD];     // y frags (A of gemm2)
__device__ __align__(16) __half g_yF_l[(size_t)BB * NN * DD];
__device__ __align__(16) __half g_W0F_h[DD * DD];
__device__ __align__(16) __half g_W0F_l[DD * DD];
__device__ __align__(16) __half g_W1F_h[DD * DD];
__device__ __align__(16) __half g_W1F_l[DD * DD];

// Frag layout: 16x16 half tile -> 512B line; lane l (0..31) holds 16B:
//   word0=(r,2c|2c+1) word1=(r+8,2c|2c+1) word2=(r,2c+8|2c+9) word3=(r+8,...)
//   r=l>>2, c=l&3.  Piece (half2) for (rho,k even): lane=((rho&7)<<2)|((k>>1)&3),
//   slot=(((k>>3)&1)<<1)|((rho>>3)&1).  tile byte base=((tileR*KT16+tileK)<<9).

// ---------------- PTX ----------------
__device__ __forceinline__ void mma_q(float* c, const uint4& a, uint32_t b0, uint32_t b1) {
    asm volatile("mma.sync.aligned.m16n8k16.row.col.f32.f16.f16.f32 "
                 "{%0,%1,%2,%3}, {%4,%5,%6,%7}, {%8,%9}, {%0,%1,%2,%3};"
                 : "+f"(c[0]), "+f"(c[1]), "+f"(c[2]), "+f"(c[3])
                 : "r"(a.x), "r"(a.y), "r"(a.z), "r"(a.w), "r"(b0), "r"(b1));
}

// ---------------- reductions ----------------
__device__ __forceinline__ float block_reduce_sum(float v, float* sh) {
    __syncthreads();
    int tid = threadIdx.x;
    #pragma unroll
    for (int o = 16; o > 0; o >>= 1) v += __shfl_down_sync(0xffffffff, v, o);
    if ((tid & 31) == 0) sh[tid >> 5] = v;
    __syncthreads();
    if (tid < 32) {
        v = (tid < (int)(blockDim.x >> 5)) ? sh[tid] : 0.0f;
        #pragma unroll
        for (int o = 16; o > 0; o >>= 1) v += __shfl_down_sync(0xffffffff, v, o);
        if (tid == 0) sh[0] = v;
    }
    __syncthreads();
    return sh[0];
}

// ---------------- fused adj pass: denom, colsum, fp16 hi/lo split to FRAG layout ----
__global__ void __launch_bounds__(256)
adj_pass_kernel(const float* __restrict__ adj, float* __restrict__ denom,
                float* __restrict__ colsum, __half* __restrict__ AhF,
                __half* __restrict__ AlF) {
    __shared__ float rowacc[128];
    const int b = blockIdx.y;
    const int r0 = blockIdx.x * 128;
    const int tid = threadIdx.x;
    const int lane = tid & 31;
    const int col0 = tid * 4;

    for (int i = tid; i < 128; i += 256) rowacc[i] = 0.0f;
    __syncthreads();

    const float* src = adj + (size_t)b * NN * NN + (size_t)r0 * NN;
    char* dh = (char*)AhF + (size_t)b * NN * NN * 2;
    char* dl = (char*)AlF + (size_t)b * NN * NN * 2;

    float cs0 = 0.f, cs1 = 0.f, cs2 = 0.f, cs3 = 0.f;
    const int tK = col0 >> 4;
    const int lane0 = (col0 >> 1) & 3;
    const int ksl = (col0 >> 3) & 1;

    for (int r = 0; r < 128; r++) {
        float4 v = *reinterpret_cast<const float4*>(&src[(size_t)r * NN + col0]);
        cs0 += v.x; cs1 += v.y; cs2 += v.z; cs3 += v.w;
        float s = (v.x + v.y) + (v.z + v.w);
        #pragma unroll
        for (int o = 16; o > 0; o >>= 1) s += __shfl_down_sync(0xffffffff, s, o);
        if (lane == 0) atomicAdd(&rowacc[r], s);

        const int rho = r0 + r;
        const int lp = ((rho & 7) << 2) | lane0;
        const int slot = (ksl << 1) | ((rho >> 3) & 1);
        size_t off = ((size_t)((rho >> 4) * (NN / 16) + tK) << 9) + (lp << 4) + (slot << 2);
        __half h0 = __float2half_rn(v.x), h1 = __float2half_rn(v.y);
        __half h2 = __float2half_rn(v.z), h3 = __float2half_rn(v.w);
        __half l0 = __float2half_rn(v.x - __half2float(h0));
        __half l1 = __float2half_rn(v.y - __half2float(h1));
        __half l2 = __float2half_rn(v.z - __half2float(h2));
        __half l3 = __float2half_rn(v.w - __half2float(h3));
        *reinterpret_cast<__half2*>(dh + off)      = __halves2half2(h0, h1);
        *reinterpret_cast<__half2*>(dh + off + 16) = __halves2half2(h2, h3);
        *reinterpret_cast<__half2*>(dl + off)      = __halves2half2(l0, l1);
        *reinterpret_cast<__half2*>(dl + off + 16) = __halves2half2(l2, l3);
    }
    __syncthreads();
    if (tid < 128) denom[(size_t)b * NN + r0 + tid] = rowacc[tid] + 1.0f;
    float* cdst = colsum + (size_t)b * NN + col0;
    atomicAdd(cdst + 0, cs0);
    atomicAdd(cdst + 1, cs1);
    atomicAdd(cdst + 2, cs2);
    atomicAdd(cdst + 3, cs3);
}

__global__ void zero_kernel(float* __restrict__ p, int n) {
    int i = blockIdx.x * blockDim.x + threadIdx.x;
    if (i < n) p[i] = 0.0f;
}

// ---------------- weights: fp32 row-major [DD][DD] -> frag hi/lo (K tiles = 32) ----
__global__ void splitW_kernel(const float* __restrict__ src, __half* __restrict__ hF,
                              __half* __restrict__ lF) {
    int i = blockIdx.x * blockDim.x + threadIdx.x;       // over DD*DD/4
    if (i >= DD * DD / 4) return;
    int r = i >> 7;                // DD/4 = 128 float4 per row
    int col0 = (i & 127) << 2;
    float4 v = reinterpret_cast<const float4*>(src)[i];
    int lp = ((r & 7) << 2) | ((col0 >> 1) & 3);
    int slot = ((((col0 >> 3) & 1)) << 1) | ((r >> 3) & 1);
    size_t off = ((size_t)((r >> 4) * (DD / 16) + (col0 >> 4)) << 9) + (lp << 4) + (slot << 2);
    __half h0 = __float2half_rn(v.x), h1 = __float2half_rn(v.y);
    __half h2 = __float2half_rn(v.z), h3 = __float2half_rn(v.w);
    __half l0 = __float2half_rn(v.x - __half2float(h0));
    __half l1 = __float2half_rn(v.y - __half2float(h1));
    __half l2 = __float2half_rn(v.z - __half2float(h2));
    __half l3 = __float2half_rn(v.w - __half2float(h3));
    char* dh = (char*)hF; char* dl = (char*)lF;
    *reinterpret_cast<__half2*>(dh + off)      = __halves2half2(h0, h1);
    *reinterpret_cast<__half2*>(dh + off + 16) = __halves2half2(h2, h3);
    *reinterpret_cast<__half2*>(dl + off)      = __halves2half2(l0, l1);
    *reinterpret_cast<__half2*>(dl + off + 16) = __halves2half2(l2, l3);
}

// ---------------- x [b][m][d] fp32 -> x^T frag hi/lo (rows=d, k=m; K tiles = 64) ----
__global__ void transpose_split(const float* __restrict__ x, __half* __restrict__ thF,
                                __half* __restrict__ tlF) {
    __shared__ float tile[32][33];
    int b = blockIdx.z;
    int m0 = blockIdx.y * 32, d0 = blockIdx.x * 32;
    const float* src = x + (size_t)b * NN * DD;
    int tx = threadIdx.x, ty = threadIdx.y;
    #pragma unroll
    for (int j = 0; j < 32; j += 8)
        tile[ty + j][tx] = src[(size_t)(m0 + ty + j) * DD + d0 + tx];
    __syncthreads();
    char* dh = (char*)thF + (size_t)b * DD * NN * 2;
    char* dl = (char*)tlF + (size_t)b * DD * NN * 2;
    int t = ty * 32 + tx;   // 0..255
    #pragma unroll
    for (int pp = 0; pp < 2; pp++) {
        int p = t + pp * 256;        // 0..511
        int rp = p >> 4;             // rho' 0..31 (d)
        int kp = p & 15;             // kappa' 0..15 (m pairs)
        float v0 = tile[kp * 2][rp];
        float v1 = tile[kp * 2 + 1][rp];
        __half h0 = __float2half_rn(v0), h1 = __float2half_rn(v1);
        __half l0 = __float2half_rn(v0 - __half2float(h0));
        __half l1 = __float2half_rn(v1 - __half2float(h1));
        int rho = d0 + rp, kg = m0 + kp * 2;
        int lp = ((rho & 7) << 2) | ((kg >> 1) & 3);
        int slot = (((kg >> 3) & 1) << 1) | ((rho >> 3) & 1);
        size_t off = ((size_t)((rho >> 4) * (NN / 16) + (kg >> 4)) << 9) + (lp << 4) + (slot << 2);
        *reinterpret_cast<__half2*>(dh + off) = __halves2half2(h0, h1);
        *reinterpret_cast<__half2*>(dl + off) = __halves2half2(l0, l1);
    }
}

// ---------------- frag-LDG HMMA GEMM: block tile 128x256, 512 threads ----------------
// D = Ah@Bh^T + Ah@Bl^T + Al@Bh^T, fp32 acc. No SMEM, no barriers.
// EPI=1 (gemm1): out = D + X -> hi/lo frag tensors (A of gemm2). KT16=64, batched.
// EPI=2 (gemm2): out = relu((D + 2*bias)/denom) -> fp32 row-major. KT16=32.
template <int KT16, int EPI>
__global__ void __launch_bounds__(512, 1)
gemm_frag(const uint4* __restrict__ AhF, const uint4* __restrict__ AlF,
          const uint4* __restrict__ BhF, const uint4* __restrict__ BlF,
          const float* __restrict__ Xadd, __half* __restrict__ OutH, __half* __restrict__ OutL,
          const float* __restrict__ bias, const float* __restrict__ denom,
          float* __restrict__ OutF) {
    const int tid = threadIdx.x;
    const int wid = tid >> 5;
    const int lane = tid & 31;
    const int m0 = (wid >> 3) * 64;     // 0/64
    const int n0 = (wid & 7) * 32;      // 0..224

    long outRow0;
    size_t batchA = 0, batchB = 0;
    if (EPI == 1) {
        int b = blockIdx.z;
        batchA = (size_t)b * (NN / 16) * (size_t)KT16 * 32;   // uint4 units
        batchB = (size_t)b * (DD / 16) * (size_t)KT16 * 32;
        outRow0 = (long)b * NN + blockIdx.y * 128;
    } else {
        outRow0 = (long)blockIdx.y * 128;
    }
    const int colBlk = blockIdx.x * 256;
    const int mTile0 = blockIdx.y * 8 + (wid >> 3) * 4;
    const int nTile0 = blockIdx.x * 16 + (wid & 7) * 2;

    const int TS = KT16 * 32;           // uint4 per row-tile strip
    const uint4* pAh = AhF + batchA + (size_t)mTile0 * TS + lane;
    const uint4* pAl = AlF + batchA + (size_t)mTile0 * TS + lane;
    const uint4* pBh = BhF + batchB + (size_t)nTile0 * TS + lane;
    const uint4* pBl = BlF + batchB + (size_t)nTile0 * TS + lane;

    float acc[4][4][4];
    #pragma unroll
    for (int a = 0; a < 4; a++)
        #pragma unroll
        for (int b2 = 0; b2 < 4; b2++)
            #pragma unroll
            for (int c = 0; c < 4; c++) acc[a][b2][c] = 0.0f;

    #pragma unroll 1
    for (int kt = 0; kt < KT16; kt++) {
        uint4 a0 = __ldg(pAh);
        uint4 a1 = __ldg(pAh + TS);
        uint4 a2 = __ldg(pAh + 2 * TS);
        uint4 a3 = __ldg(pAh + 3 * TS);
        uint4 b0h = __ldg(pBh);
        uint4 b1h = __ldg(pBh + TS);
        uint4 b0l = __ldg(pBl);
        uint4 b1l = __ldg(pBl + TS);
        // ah x bh
        mma_q(acc[0][0], a0, b0h.x, b0h.z); mma_q(acc[0][1], a0, b0h.y, b0h.w);
        mma_q(acc[0][2], a0, b1h.x, b1h.z); mma_q(acc[0][3], a0, b1h.y, b1h.w);
        mma_q(acc[1][0], a1, b0h.x, b0h.z); mma_q(acc[1][1], a1, b0h.y, b0h.w);
        mma_q(acc[1][2], a1, b1h.x, b1h.z); mma_q(acc[1][3], a1, b1h.y, b1h.w);
        mma_q(acc[2][0], a2, b0h.x, b0h.z); mma_q(acc[2][1], a2, b0h.y, b0h.w);
        mma_q(acc[2][2], a2, b1h.x, b1h.z); mma_q(acc[2][3], a2, b1h.y, b1h.w);
        mma_q(acc[3][0], a3, b0h.x, b0h.z); mma_q(acc[3][1], a3, b0h.y, b0h.w);
        mma_q(acc[3][2], a3, b1h.x, b1h.z); mma_q(acc[3][3], a3, b1h.y, b1h.w);
        // ah x bl
        mma_q(acc[0][0], a0, b0l.x, b0l.z); mma_q(acc[0][1], a0, b0l.y, b0l.w);
        mma_q(acc[0][2], a0, b1l.x, b1l.z); mma_q(acc[0][3], a0, b1l.y, b1l.w);
        mma_q(acc[1][0], a1, b0l.x, b0l.z); mma_q(acc[1][1], a1, b0l.y, b0l.w);
        mma_q(acc[1][2], a1, b1l.x, b1l.z); mma_q(acc[1][3], a1, b1l.y, b1l.w);
        mma_q(acc[2][0], a2, b0l.x, b0l.z); mma_q(acc[2][1], a2, b0l.y, b0l.w);
        mma_q(acc[2][2], a2, b1l.x, b1l.z); mma_q(acc[2][3], a2, b1l.y, b1l.w);
        mma_q(acc[3][0], a3, b0l.x, b0l.z); mma_q(acc[3][1], a3, b0l.y, b0l.w);
        mma_q(acc[3][2], a3, b1l.x, b1l.z); mma_q(acc[3][3], a3, b1l.y, b1l.w);
        // al x bh (reuse a regs)
        a0 = __ldg(pAl); a1 = __ldg(pAl + TS); a2 = __ldg(pAl + 2 * TS); a3 = __ldg(pAl + 3 * TS);
        mma_q(acc[0][0], a0, b0h.x, b0h.z); mma_q(acc[0][1], a0, b0h.y, b0h.w);
        mma_q(acc[0][2], a0, b1h.x, b1h.z); mma_q(acc[0][3], a0, b1h.y, b1h.w);
        mma_q(acc[1][0], a1, b0h.x, b0h.z); mma_q(acc[1][1], a1, b0h.y, b0h.w);
        mma_q(acc[1][2], a1, b1h.x, b1h.z); mma_q(acc[1][3], a1, b1h.y, b1h.w);
        mma_q(acc[2][0], a2, b0h.x, b0h.z); mma_q(acc[2][1], a2, b0h.y, b0h.w);
        mma_q(acc[2][2], a2, b1h.x, b1h.z); mma_q(acc[2][3], a2, b1h.y, b1h.w);
        mma_q(acc[3][0], a3, b0h.x, b0h.z); mma_q(acc[3][1], a3, b0h.y, b0h.w);
        mma_q(acc[3][2], a3, b1h.x, b1h.z); mma_q(acc[3][3], a3, b1h.y, b1h.w);
        pAh += 32; pAl += 32; pBh += 32; pBl += 32;
    }

    // ---- epilogue ----
    const int rr = lane >> 2;
    const int cc = (lane & 3) * 2;
    if (EPI == 1) {
        const int tR0 = (int)((outRow0 + m0) >> 4);
        const int tK0 = (colBlk + n0) >> 4;
        char* oh = (char*)OutH;
        char* ol = (char*)OutL;
        #pragma unroll
        for (int mf = 0; mf < 4; mf++) {
            #pragma unroll
            for (int hf = 0; hf < 2; hf++) {
                long grow = outRow0 + m0 + mf * 16 + rr + hf * 8;
                #pragma unroll
                for (int nf = 0; nf < 4; nf++) {
                    int gcol = colBlk + n0 + nf * 8 + cc;
                    float v0 = acc[mf][nf][hf * 2 + 0];
                    float v1 = acc[mf][nf][hf * 2 + 1];
                    float2 xv = *reinterpret_cast<const float2*>(&Xadd[(size_t)grow * DD + gcol]);
                    v0 += xv.x; v1 += xv.y;
                    __half h0 = __float2half_rn(v0), h1 = __float2half_rn(v1);
                    __half l0 = __float2half_rn(v0 - __half2float(h0));
                    __half l1 = __float2half_rn(v1 - __half2float(h1));
                    size_t off = ((size_t)((tR0 + mf) * (DD / 16) + tK0 + (nf >> 1)) << 9)
                                 + (lane << 4) + (((nf & 1) * 2 + hf) << 2);
                    *reinterpret_cast<__half2*>(oh + off) = __halves2half2(h0, h1);
                    *reinterpret_cast<__half2*>(ol + off) = __halves2half2(l0, l1);
                }
            }
        }
    } else {
        #pragma unroll
        for (int mf = 0; mf < 4; mf++) {
            #pragma unroll
            for (int hf = 0; hf < 2; hf++) {
                long grow = outRow0 + m0 + mf * 16 + rr + hf * 8;
                float invd = 1.0f / denom[grow];
                #pragma unroll
                for (int nf = 0; nf < 4; nf++) {
                    int gcol = colBlk + n0 + nf * 8 + cc;
                    float2 bv = *reinterpret_cast<const float2*>(&bias[gcol]);
                    float2 o;
                    o.x = fmaxf((acc[mf][nf][hf * 2 + 0] + 2.0f * bv.x) * invd, 0.0f);
                    o.y = fmaxf((acc[mf][nf][hf * 2 + 1] + 2.0f * bv.y) * invd, 0.0f);
                    *reinterpret_cast<float2*>(&OutF[(size_t)grow * DD + gcol]) = o;
                }
            }
        }
    }
}

// ---------------- LayerNorm ----------------
__global__ void ln_kernel(const float* __restrict__ X, const float* __restrict__ g,
                          const float* __restrict__ b, float* __restrict__ out) {
    __shared__ float sh[32];
    const int row = blockIdx.x;
    const float* p = X + (size_t)row * DD;
    const int tid = threadIdx.x;
    float v0 = p[tid];
    float v1 = p[tid + 256];
    float mu = block_reduce_sum(v0 + v1, sh) * (1.0f / DD);
    float d0 = v0 - mu, d1 = v1 - mu;
    float var = block_reduce_sum(d0 * d0 + d1 * d1, sh) * (1.0f / DD);
    float r = rsqrtf(var + LN_EPS);
    out[(size_t)row * DD + tid] = d0 * r * g[tid] + b[tid];
    out[(size_t)row * DD + tid + 256] = d1 * r * g[tid + 256] + b[tid + 256];
}

__global__ void mask_kernel(const float* __restrict__ denom, const float* __restrict__ colsum,
                            float* __restrict__ out, int count) {
    int i = blockIdx.x * blockDim.x + threadIdx.x;
    if (i >= count) return;
    if (i < BB * NN) {
        float rs = denom[i] - 1.0f;
        out[i] = ((rs + colsum[i]) == 0.0f) ? 1.0f : 0.0f;
    } else {
        out[i] = 0.0f;
    }
}

// ---------------- launch ----------------
extern "C" void kernel_launch(void* const* d_in, const int* in_sizes, int n_in,
                              void* d_out, int out_size) {
    const float* adj = (const float*)d_in[0];
    const float* emb = (const float*)d_in[1];
    const float* W0w = (const float*)d_in[3];
    const float* W0b = (const float*)d_in[4];
    const float* W1w = (const float*)d_in[5];
    const float* W1b = (const float*)d_in[6];
    const float* lng = (const float*)d_in[7];
    const float* lnb = (const float*)d_in[8];
    float* out = (float*)d_out;

    float *denom, *colsum, *x;
    __half *adjh, *adjl, *xth, *xtl, *yh, *yl, *w0h, *w0l, *w1h, *w1l;
    cudaGetSymbolAddress((void**)&denom, g_denom);
    cudaGetSymbolAddress((void**)&colsum, g_colsum);
    cudaGetSymbolAddress((void**)&x, g_x);
    cudaGetSymbolAddress((void**)&adjh, g_adjF_h);
    cudaGetSymbolAddress((void**)&adjl, g_adjF_l);
    cudaGetSymbolAddress((void**)&xth, g_xTF_h);
    cudaGetSymbolAddress((void**)&xtl, g_xTF_l);
    cudaGetSymbolAddress((void**)&yh, g_yF_h);
    cudaGetSymbolAddress((void**)&yl, g_yF_l);
    cudaGetSymbolAddress((void**)&w0h, g_W0F_h);
    cudaGetSymbolAddress((void**)&w0l, g_W0F_l);
    cudaGetSymbolAddress((void**)&w1h, g_W1F_h);
    cudaGetSymbolAddress((void**)&w1l, g_W1F_l);

    dim3 tg(DD / 32, NN / 32, BB);
    dim3 tb(32, 8);
    dim3 ga(8, BB);
    dim3 g1(DD / 256, NN / 128, BB);        // (2, 8, 32)
    dim3 g2(DD / 256, (BB * NN) / 128, 1);  // (2, 256)
    int wq = (DD * DD / 4 + 255) / 256;

    zero_kernel<<<(BB * NN + 255) / 256, 256>>>(colsum, BB * NN);                 // 1
    adj_pass_kernel<<<ga, 256>>>(adj, denom, colsum, adjh, adjl);                 // 2
    transpose_split<<<tg, tb>>>(emb, xth, xtl);                                   // 3
    splitW_kernel<<<wq, 256>>>(W0w, w0h, w0l);                                    // 4
    splitW_kernel<<<wq, 256>>>(W1w, w1h, w1l);                                    // 5
    // layer 0
    gemm_frag<64, 1><<<g1, 512>>>((const uint4*)adjh, (const uint4*)adjl,
                                  (const uint4*)xth, (const uint4*)xtl,
                                  emb, yh, yl, nullptr, nullptr, nullptr);        // 6
    gemm_frag<32, 2><<<g2, 512>>>((const uint4*)yh, (const uint4*)yl,
                                  (const uint4*)w0h, (const uint4*)w0l,
                                  nullptr, nullptr, nullptr, W0b, denom, x);      // 7
    // layer 1
    transpose_split<<<tg, tb>>>(x, xth, xtl);                                     // 8
    gemm_frag<64, 1><<<g1, 512>>>((const uint4*)adjh, (const uint4*)adjl,
                                  (const uint4*)xth, (const uint4*)xtl,
                                  x, yh, yl, nullptr, nullptr, nullptr);          // 9
    gemm_frag<32, 2><<<g2, 512>>>((const uint4*)yh, (const uint4*)yl,
                                  (const uint4*)w1h, (const uint4*)w1l,
                                  nullptr, nullptr, nullptr, W1b, denom, x);      // 10

    ln_kernel<<<BB * NN, 256>>>(x, lng, lnb, out);                                // 11

    int extra = out_size - BB * NN * DD;
    if (extra > 0) {
        mask_kernel<<<(extra + 255) / 256, 256>>>(denom, colsum,
                                                  out + (size_t)BB * NN * DD, extra);
    }
}

// round 8
// speedup vs baseline: 1.2117x; 1.2117x over previous
#include <cuda_runtime.h>
#include <cuda_fp16.h>
#include <cstdint>

#define BB 32
#define NN 1024
#define DD 512
#define LN_EPS 1e-5f

// ---------------- scratch (no allocations allowed) ----------------
__device__ float  g_denom[BB * NN];
__device__ float  g_colsum[BB * NN];
__device__ float  g_x[BB * NN * DD];                 // fp32 layer activations
__device__ __half g_adj_h[(size_t)BB * NN * NN];     // adj split
__device__ __half g_adj_l[(size_t)BB * NN * NN];
__device__ __half g_xT_h[(size_t)BB * DD * NN];      // X^T split (B operand of gemm1)
__device__ __half g_xT_l[(size_t)BB * DD * NN];
__device__ __half g_y_h[(size_t)BB * NN * DD];       // gemm1 output split (A of gemm2)
__device__ __half g_y_l[(size_t)BB * NN * DD];
__device__ __half g_W0_h[DD * DD];
__device__ __half g_W0_l[DD * DD];
__device__ __half g_W1_h[DD * DD];
__device__ __half g_W1_l[DD * DD];

// ---------------- PTX helpers (base sm_103-safe) ----------------
__device__ __forceinline__ uint32_t smem_u32(const void* p) {
    uint32_t a;
    asm("{ .reg .u64 t; cvta.to.shared.u64 t, %1; cvt.u32.u64 %0, t; }" : "=r"(a) : "l"(p));
    return a;
}
__device__ __forceinline__ void cp_async16(uint32_t dst, const void* src) {
    asm volatile("cp.async.cg.shared.global [%0], [%1], 16;" :: "r"(dst), "l"(src));
}
__device__ __forceinline__ void cp_commit() { asm volatile("cp.async.commit_group;" ::: "memory"); }
template <int N>
__device__ __forceinline__ void cp_wait() { asm volatile("cp.async.wait_group %0;" :: "n"(N) : "memory"); }

__device__ __forceinline__ void ldsm4(uint32_t* r, uint32_t addr) {
    asm volatile("ldmatrix.sync.aligned.m8n8.x4.shared.b16 {%0,%1,%2,%3}, [%4];"
                 : "=r"(r[0]), "=r"(r[1]), "=r"(r[2]), "=r"(r[3]) : "r"(addr));
}
// fp32-accumulate (full precision main term, rt~16)
__device__ __forceinline__ void mma16816(float* c, const uint32_t* a, const uint32_t* b) {
    asm volatile("mma.sync.aligned.m16n8k16.row.col.f32.f16.f16.f32 "
                 "{%0,%1,%2,%3}, {%4,%5,%6,%7}, {%8,%9}, {%0,%1,%2,%3};"
                 : "+f"(c[0]), "+f"(c[1]), "+f"(c[2]), "+f"(c[3])
                 : "r"(a[0]), "r"(a[1]), "r"(a[2]), "r"(a[3]), "r"(b[0]), "r"(b[1]));
}
// fp16-accumulate (cross terms, rt~8 = 2x faster)
__device__ __forceinline__ void mma16816h(uint32_t* c, const uint32_t* a, const uint32_t* b) {
    asm volatile("mma.sync.aligned.m16n8k16.row.col.f16.f16.f16.f16 "
                 "{%0,%1}, {%2,%3,%4,%5}, {%6,%7}, {%0,%1};"
                 : "+r"(c[0]), "+r"(c[1])
                 : "r"(a[0]), "r"(a[1]), "r"(a[2]), "r"(a[3]), "r"(b[0]), "r"(b[1]));
}

// ---------------- reductions ----------------
__device__ __forceinline__ float block_reduce_sum(float v, float* sh) {
    __syncthreads();
    int tid = threadIdx.x;
    #pragma unroll
    for (int o = 16; o > 0; o >>= 1) v += __shfl_down_sync(0xffffffff, v, o);
    if ((tid & 31) == 0) sh[tid >> 5] = v;
    __syncthreads();
    if (tid < 32) {
        v = (tid < (int)(blockDim.x >> 5)) ? sh[tid] : 0.0f;
        #pragma unroll
        for (int o = 16; o > 0; o >>= 1) v += __shfl_down_sync(0xffffffff, v, o);
        if (tid == 0) sh[0] = v;
    }
    __syncthreads();
    return sh[0];
}

// ---------------- fused adj pass: rowsum+1 -> denom, colsum (atomic), fp16 split ----
__global__ void __launch_bounds__(256)
adj_pass_kernel(const float* __restrict__ adj, float* __restrict__ denom,
                float* __restrict__ colsum, __half* __restrict__ Ah,
                __half* __restrict__ Al) {
    __shared__ float rowacc[128];
    const int b = blockIdx.y;
    const int r0 = blockIdx.x * 128;
    const int tid = threadIdx.x;
    const int lane = tid & 31;
    const int col0 = tid * 4;

    for (int i = tid; i < 128; i += 256) rowacc[i] = 0.0f;
    __syncthreads();

    const float* src = adj + (size_t)b * NN * NN + (size_t)r0 * NN;
    __half* dh = Ah + (size_t)b * NN * NN + (size_t)r0 * NN;
    __half* dl = Al + (size_t)b * NN * NN + (size_t)r0 * NN;

    float cs0 = 0.f, cs1 = 0.f, cs2 = 0.f, cs3 = 0.f;

    for (int r = 0; r < 128; r++) {
        float4 v = *reinterpret_cast<const float4*>(&src[(size_t)r * NN + col0]);
        __half h0 = __float2half_rn(v.x), h1 = __float2half_rn(v.y);
        __half h2 = __float2half_rn(v.z), h3 = __float2half_rn(v.w);
        __half l0 = __float2half_rn(v.x - __half2float(h0));
        __half l1 = __float2half_rn(v.y - __half2float(h1));
        __half l2 = __float2half_rn(v.z - __half2float(h2));
        __half l3 = __float2half_rn(v.w - __half2float(h3));
        *reinterpret_cast<__half2*>(&dh[(size_t)r * NN + col0])     = __halves2half2(h0, h1);
        *reinterpret_cast<__half2*>(&dh[(size_t)r * NN + col0 + 2]) = __halves2half2(h2, h3);
        *reinterpret_cast<__half2*>(&dl[(size_t)r * NN + col0])     = __halves2half2(l0, l1);
        *reinterpret_cast<__half2*>(&dl[(size_t)r * NN + col0 + 2]) = __halves2half2(l2, l3);
        cs0 += v.x; cs1 += v.y; cs2 += v.z; cs3 += v.w;
        float s = (v.x + v.y) + (v.z + v.w);
        #pragma unroll
        for (int o = 16; o > 0; o >>= 1) s += __shfl_down_sync(0xffffffff, s, o);
        if (lane == 0) atomicAdd(&rowacc[r], s);
    }
    __syncthreads();
    if (tid < 128) denom[(size_t)b * NN + r0 + tid] = rowacc[tid] + 1.0f;
    float* cdst = colsum + (size_t)b * NN + col0;
    atomicAdd(cdst + 0, cs0);
    atomicAdd(cdst + 1, cs1);
    atomicAdd(cdst + 2, cs2);
    atomicAdd(cdst + 3, cs3);
}

__global__ void zero_kernel(float* __restrict__ p, int n) {
    int i = blockIdx.x * blockDim.x + threadIdx.x;
    if (i < n) p[i] = 0.0f;
}

__global__ void split_kernel(const float* __restrict__ src, __half* __restrict__ h,
                             __half* __restrict__ l, int n4) {
    int i = blockIdx.x * blockDim.x + threadIdx.x;
    if (i >= n4) return;
    float4 v = reinterpret_cast<const float4*>(src)[i];
    __half h0 = __float2half_rn(v.x), h1 = __float2half_rn(v.y);
    __half h2 = __float2half_rn(v.z), h3 = __float2half_rn(v.w);
    __half l0 = __float2half_rn(v.x - __half2float(h0));
    __half l1 = __float2half_rn(v.y - __half2float(h1));
    __half l2 = __float2half_rn(v.z - __half2float(h2));
    __half l3 = __float2half_rn(v.w - __half2float(h3));
    reinterpret_cast<__half2*>(h)[i * 2 + 0] = __halves2half2(h0, h1);
    reinterpret_cast<__half2*>(h)[i * 2 + 1] = __halves2half2(h2, h3);
    reinterpret_cast<__half2*>(l)[i * 2 + 0] = __halves2half2(l0, l1);
    reinterpret_cast<__half2*>(l)[i * 2 + 1] = __halves2half2(l2, l3);
}

__global__ void transpose_split(const float* __restrict__ x, __half* __restrict__ th,
                                __half* __restrict__ tl) {
    __shared__ float tile[32][33];
    int b = blockIdx.z;
    int m0 = blockIdx.y * 32, d0 = blockIdx.x * 32;
    const float* src = x + (size_t)b * NN * DD;
    int tx = threadIdx.x, ty = threadIdx.y;
    #pragma unroll
    for (int j = 0; j < 32; j += 8)
        tile[ty + j][tx] = src[(size_t)(m0 + ty + j) * DD + d0 + tx];
    __syncthreads();
    __half* dh = th + (size_t)b * DD * NN;
    __half* dl = tl + (size_t)b * DD * NN;
    #pragma unroll
    for (int j = 0; j < 32; j += 8) {
        float v = tile[tx][ty + j];
        __half h = __float2half_rn(v);
        __half l = __float2half_rn(v - __half2float(h));
        dh[(size_t)(d0 + ty + j) * NN + m0 + tx] = h;
        dl[(size_t)(d0 + ty + j) * NN + m0 + tx] = l;
    }
}

// ---------------- HMMA GEMM: 128x128 block tile, K-chunks of 64 ----------------
// D = Ah@Bh^T (fp32 acc) + [Ah@Bl^T + Al@Bh^T] (shared fp16 acc, 2x rate).
#define KT 64
#define TBYTES 16384
#define STAGE_BYTES (4 * TBYTES)
#define GEMM_SMEM (2 * STAGE_BYTES)

template <int KTOT, int EPI>
__global__ void __launch_bounds__(256, 1)
gemm_hmma(const __half* __restrict__ Ah, const __half* __restrict__ Al,
          const __half* __restrict__ Bh, const __half* __restrict__ Bl,
          const float* __restrict__ Xadd, __half* __restrict__ OutH, __half* __restrict__ OutL,
          const float* __restrict__ bias, const float* __restrict__ denom,
          float* __restrict__ OutF) {
    extern __shared__ char smem[];
    const uint32_t sb = smem_u32(smem);
    const int tid = threadIdx.x;
    const int wid = tid >> 5;
    const int lane = tid & 31;

    long aRow0, bRow0, outRow0;
    if (EPI == 1) {
        int b = blockIdx.z;
        aRow0 = (long)b * NN + blockIdx.y * 128;
        bRow0 = (long)b * DD + blockIdx.x * 128;
        outRow0 = aRow0;
    } else {
        aRow0 = (long)blockIdx.y * 128;
        bRow0 = (long)blockIdx.x * 128;
        outRow0 = aRow0;
    }
    const int colBlk = blockIdx.x * 128;

    const __half* srcA_h = Ah + aRow0 * KTOT;
    const __half* srcA_l = Al + aRow0 * KTOT;
    const __half* srcB_h = Bh + bRow0 * KTOT;
    const __half* srcB_l = Bl + bRow0 * KTOT;

    const int m0 = (wid >> 2) * 64;
    const int n0 = (wid & 3) * 32;

    const int ltile = lane >> 3;
    const int rowInTile = (lane & 7) + ((ltile & 1) << 3);
    const int kk = ltile >> 1;
    const int lx = lane & 7;

    float acc[4][4][4];                 // main term, fp32
    uint32_t cacc[4][4][2];             // cross terms, fp16 (half2 x2)
    #pragma unroll
    for (int a = 0; a < 4; a++)
        #pragma unroll
        for (int b2 = 0; b2 < 4; b2++) {
            #pragma unroll
            for (int c = 0; c < 4; c++) acc[a][b2][c] = 0.0f;
            cacc[a][b2][0] = 0u; cacc[a][b2][1] = 0u;
        }

    const int nk = KTOT / KT;

    auto issue = [&](int i) {
        const uint32_t stg = sb + (uint32_t)(i & 1) * STAGE_BYTES;
        const int k0 = i * KT;
        #pragma unroll
        for (int t = 0; t < 4; t++) {
            const __half* base = (t == 0) ? srcA_h : (t == 1) ? srcA_l
                               : (t == 2) ? srcB_h : srcB_l;
            #pragma unroll
            for (int jj = 0; jj < 4; jj++) {
                int cid = tid + jj * 256;
                int row = cid >> 3, c = cid & 7;
                cp_async16(stg + t * TBYTES + row * 128 + ((c ^ (row & 7)) << 4),
                           base + (size_t)row * KTOT + k0 + c * 8);
            }
        }
        cp_commit();
    };

    issue(0);

    for (int i = 0; i < nk; i++) {
        if (i + 1 < nk) issue(i + 1);
        if (i + 1 < nk) cp_wait<1>(); else cp_wait<0>();
        __syncthreads();

        const uint32_t stg = sb + (uint32_t)(i & 1) * STAGE_BYTES;
        const uint32_t sAh = stg, sAl = stg + TBYTES, sBh = stg + 2 * TBYTES, sBl = stg + 3 * TBYTES;

        #pragma unroll
        for (int ks = 0; ks < 4; ks++) {
            const uint32_t swz = (uint32_t)(((ks * 2 + kk) ^ lx) << 4);
            uint32_t af[4][4], bh[4][2], bl[4][2];
            // phase 1: A-hi fragments + both B fragments
            #pragma unroll
            for (int mf = 0; mf < 4; mf++) {
                uint32_t off = (uint32_t)((m0 + mf * 16 + rowInTile) * 128) + swz;
                ldsm4(af[mf], sAh + off);
            }
            #pragma unroll
            for (int nh = 0; nh < 2; nh++) {
                uint32_t off = (uint32_t)((n0 + nh * 16 + rowInTile) * 128) + swz;
                uint32_t r[4], s[4];
                ldsm4(r, sBh + off);
                ldsm4(s, sBl + off);
                bh[nh * 2][0] = r[0]; bh[nh * 2][1] = r[2];
                bh[nh * 2 + 1][0] = r[1]; bh[nh * 2 + 1][1] = r[3];
                bl[nh * 2][0] = s[0]; bl[nh * 2][1] = s[2];
                bl[nh * 2 + 1][0] = s[1]; bl[nh * 2 + 1][1] = s[3];
            }
            // main: fp32 acc
            #pragma unroll
            for (int mf = 0; mf < 4; mf++)
                #pragma unroll
                for (int nf = 0; nf < 4; nf++)
                    mma16816(acc[mf][nf], af[mf], bh[nf]);
            // cross 1: Ah x Bl, fp16 acc
            #pragma unroll
            for (int mf = 0; mf < 4; mf++)
                #pragma unroll
                for (int nf = 0; nf < 4; nf++)
                    mma16816h(cacc[mf][nf], af[mf], bl[nf]);
            // phase 2: overwrite fragments with A-lo
            #pragma unroll
            for (int mf = 0; mf < 4; mf++) {
                uint32_t off = (uint32_t)((m0 + mf * 16 + rowInTile) * 128) + swz;
                ldsm4(af[mf], sAl + off);
            }
            // cross 2: Al x Bh, fp16 acc (same accumulator)
            #pragma unroll
            for (int mf = 0; mf < 4; mf++)
                #pragma unroll
                for (int nf = 0; nf < 4; nf++)
                    mma16816h(cacc[mf][nf], af[mf], bh[nf]);
        }
        __syncthreads();
    }

    // ---- epilogue ----
    const int rr = lane >> 2;
    const int cc = (lane & 3) * 2;
    #pragma unroll
    for (int mf = 0; mf < 4; mf++) {
        #pragma unroll
        for (int hf = 0; hf < 2; hf++) {
            long grow = outRow0 + m0 + mf * 16 + rr + hf * 8;
            float invd = (EPI == 2) ? (1.0f / denom[grow]) : 0.0f;
            #pragma unroll
            for (int nf = 0; nf < 4; nf++) {
                int gcol = colBlk + n0 + nf * 8 + cc;
                size_t gi = (size_t)grow * DD + gcol;
                __half2 cr = *reinterpret_cast<__half2*>(&cacc[mf][nf][hf]);
                float v0 = acc[mf][nf][hf * 2 + 0] + __low2float(cr);
                float v1 = acc[mf][nf][hf * 2 + 1] + __high2float(cr);
                if (EPI == 1) {
                    float2 xv = *reinterpret_cast<const float2*>(&Xadd[gi]);
                    v0 += xv.x; v1 += xv.y;
                    __half h0 = __float2half_rn(v0), h1 = __float2half_rn(v1);
                    __half l0 = __float2half_rn(v0 - __half2float(h0));
                    __half l1 = __float2half_rn(v1 - __half2float(h1));
                    *reinterpret_cast<__half2*>(&OutH[gi]) = __halves2half2(h0, h1);
                    *reinterpret_cast<__half2*>(&OutL[gi]) = __halves2half2(l0, l1);
                } else {
                    float2 bv = *reinterpret_cast<const float2*>(&bias[gcol]);
                    float2 o;
                    o.x = fmaxf((v0 + 2.0f * bv.x) * invd, 0.0f);
                    o.y = fmaxf((v1 + 2.0f * bv.y) * invd, 0.0f);
                    *reinterpret_cast<float2*>(&OutF[gi]) = o;
                }
            }
        }
    }
}

// ---------------- LayerNorm ----------------
__global__ void ln_kernel(const float* __restrict__ X, const float* __restrict__ g,
                          const float* __restrict__ b, float* __restrict__ out) {
    __shared__ float sh[32];
    const int row = blockIdx.x;
    const float* p = X + (size_t)row * DD;
    const int tid = threadIdx.x;
    float v0 = p[tid];
    float v1 = p[tid + 256];
    float mu = block_reduce_sum(v0 + v1, sh) * (1.0f / DD);
    float d0 = v0 - mu, d1 = v1 - mu;
    float var = block_reduce_sum(d0 * d0 + d1 * d1, sh) * (1.0f / DD);
    float r = rsqrtf(var + LN_EPS);
    out[(size_t)row * DD + tid] = d0 * r * g[tid] + b[tid];
    out[(size_t)row * DD + tid + 256] = d1 * r * g[tid + 256] + b[tid + 256];
}

__global__ void mask_kernel(const float* __restrict__ denom, const float* __restrict__ colsum,
                            float* __restrict__ out, int count) {
    int i = blockIdx.x * blockDim.x + threadIdx.x;
    if (i >= count) return;
    if (i < BB * NN) {
        float rs = denom[i] - 1.0f;
        out[i] = ((rs + colsum[i]) == 0.0f) ? 1.0f : 0.0f;
    } else {
        out[i] = 0.0f;
    }
}

// ---------------- launch ----------------
extern "C" void kernel_launch(void* const* d_in, const int* in_sizes, int n_in,
                              void* d_out, int out_size) {
    const float* adj = (const float*)d_in[0];
    const float* emb = (const float*)d_in[1];
    const float* W0w = (const float*)d_in[3];
    const float* W0b = (const float*)d_in[4];
    const float* W1w = (const float*)d_in[5];
    const float* W1b = (const float*)d_in[6];
    const float* lng = (const float*)d_in[7];
    const float* lnb = (const float*)d_in[8];
    float* out = (float*)d_out;

    float *denom, *colsum, *x;
    __half *adjh, *adjl, *xth, *xtl, *yh, *yl, *w0h, *w0l, *w1h, *w1l;
    cudaGetSymbolAddress((void**)&denom, g_denom);
    cudaGetSymbolAddress((void**)&colsum, g_colsum);
    cudaGetSymbolAddress((void**)&x, g_x);
    cudaGetSymbolAddress((void**)&adjh, g_adj_h);
    cudaGetSymbolAddress((void**)&adjl, g_adj_l);
    cudaGetSymbolAddress((void**)&xth, g_xT_h);
    cudaGetSymbolAddress((void**)&xtl, g_xT_l);
    cudaGetSymbolAddress((void**)&yh, g_y_h);
    cudaGetSymbolAddress((void**)&yl, g_y_l);
    cudaGetSymbolAddress((void**)&w0h, g_W0_h);
    cudaGetSymbolAddress((void**)&w0l, g_W0_l);
    cudaGetSymbolAddress((void**)&w1h, g_W1_h);
    cudaGetSymbolAddress((void**)&w1l, g_W1_l);

    cudaFuncSetAttribute(gemm_hmma<1024, 1>, cudaFuncAttributeMaxDynamicSharedMemorySize, GEMM_SMEM);
    cudaFuncSetAttribute(gemm_hmma<512, 2>, cudaFuncAttributeMaxDynamicSharedMemorySize, GEMM_SMEM);

    dim3 tg(DD / 32, NN / 32, BB);
    dim3 tb(32, 8);
    dim3 ga(8, BB);
    dim3 g1(DD / 128, NN / 128, BB);        // (4, 8, 32)
    dim3 g2(DD / 128, (BB * NN) / 128, 1);  // (4, 256)
    int w4 = (DD * DD) / 4;

    zero_kernel<<<(BB * NN + 255) / 256, 256>>>(colsum, BB * NN);              // 1
    adj_pass_kernel<<<ga, 256>>>(adj, denom, colsum, adjh, adjl);              // 2
    transpose_split<<<tg, tb>>>(emb, xth, xtl);                                // 3
    gemm_hmma<1024, 1><<<g1, 256, GEMM_SMEM>>>(adjh, adjl, xth, xtl, emb, yh, yl,
                                               nullptr, nullptr, nullptr);     // 4
    split_kernel<<<(w4 + 255) / 256, 256>>>(W0w, w0h, w0l, w4);                // 5
    gemm_hmma<512, 2><<<g2, 256, GEMM_SMEM>>>(yh, yl, w0h, w0l, nullptr, nullptr, nullptr,
                                              W0b, denom, x);                  // 6
    split_kernel<<<(w4 + 255) / 256, 256>>>(W1w, w1h, w1l, w4);                // 7
    transpose_split<<<tg, tb>>>(x, xth, xtl);                                  // 8
    gemm_hmma<1024, 1><<<g1, 256, GEMM_SMEM>>>(adjh, adjl, xth, xtl, x, yh, yl,
                                               nullptr, nullptr, nullptr);     // 9
    gemm_hmma<512, 2><<<g2, 256, GEMM_SMEM>>>(yh, yl, w1h, w1l, nullptr, nullptr, nullptr,
                                              W1b, denom, x);                  // 10

    ln_kernel<<<BB * NN, 256>>>(x, lng, lnb, out);                             // 11

    int extra = out_size - BB * NN * DD;
    if (extra > 0) {
        mask_kernel<<<(extra + 255) / 256, 256>>>(denom, colsum,
                                                  out + (size_t)BB * NN * DD, extra);
    }
}

// round 9
// speedup vs baseline: 1.3247x; 1.0933x over previous
#include <cuda_runtime.h>
#include <cuda_fp16.h>
#include <cstdint>

#define BB 32
#define NN 1024
#define DD 512
#define LN_EPS 1e-5f

// ---------------- scratch (no allocations allowed) ----------------
__device__ float  g_denom[BB * NN];
__device__ float  g_colsum[BB * NN];
__device__ float  g_x[BB * NN * DD];                 // fp32 layer activations
__device__ __half g_adj_h[(size_t)BB * NN * NN];     // adj split
__device__ __half g_adj_l[(size_t)BB * NN * NN];
__device__ __half g_xT_h[(size_t)BB * DD * NN];      // X^T split (B operand of gemm1)
__device__ __half g_xT_l[(size_t)BB * DD * NN];
__device__ __half g_y_h[(size_t)BB * NN * DD];       // gemm1 output split (A of gemm2)
__device__ __half g_y_l[(size_t)BB * NN * DD];
__device__ __half g_W0_h[DD * DD];
__device__ __half g_W0_l[DD * DD];
__device__ __half g_W1_h[DD * DD];
__device__ __half g_W1_l[DD * DD];

// ---------------- PTX helpers (base sm_103-safe) ----------------
__device__ __forceinline__ uint32_t smem_u32(const void* p) {
    uint32_t a;
    asm("{ .reg .u64 t; cvta.to.shared.u64 t, %1; cvt.u32.u64 %0, t; }" : "=r"(a) : "l"(p));
    return a;
}
__device__ __forceinline__ void cp_async16(uint32_t dst, const void* src) {
    asm volatile("cp.async.cg.shared.global [%0], [%1], 16;" :: "r"(dst), "l"(src));
}
__device__ __forceinline__ void cp_commit() { asm volatile("cp.async.commit_group;" ::: "memory"); }
template <int N>
__device__ __forceinline__ void cp_wait() { asm volatile("cp.async.wait_group %0;" :: "n"(N) : "memory"); }

__device__ __forceinline__ void ldsm4(uint32_t* r, uint32_t addr) {
    asm volatile("ldmatrix.sync.aligned.m8n8.x4.shared.b16 {%0,%1,%2,%3}, [%4];"
                 : "=r"(r[0]), "=r"(r[1]), "=r"(r[2]), "=r"(r[3]) : "r"(addr));
}
// fp32-accumulate (full precision main term, rt~15)
__device__ __forceinline__ void mma16816(float* c, const uint32_t* a, const uint32_t* b) {
    asm volatile("mma.sync.aligned.m16n8k16.row.col.f32.f16.f16.f32 "
                 "{%0,%1,%2,%3}, {%4,%5,%6,%7}, {%8,%9}, {%0,%1,%2,%3};"
                 : "+f"(c[0]), "+f"(c[1]), "+f"(c[2]), "+f"(c[3])
                 : "r"(a[0]), "r"(a[1]), "r"(a[2]), "r"(a[3]), "r"(b[0]), "r"(b[1]));
}
// fp16-accumulate (cross terms, rt~8 = 2x faster)
__device__ __forceinline__ void mma16816h(uint32_t* c, const uint32_t* a, const uint32_t* b) {
    asm volatile("mma.sync.aligned.m16n8k16.row.col.f16.f16.f16.f16 "
                 "{%0,%1}, {%2,%3,%4,%5}, {%6,%7}, {%0,%1};"
                 : "+r"(c[0]), "+r"(c[1])
                 : "r"(a[0]), "r"(a[1]), "r"(a[2]), "r"(a[3]), "r"(b[0]), "r"(b[1]));
}

// ---------------- reductions ----------------
__device__ __forceinline__ float block_reduce_sum(float v, float* sh) {
    __syncthreads();
    int tid = threadIdx.x;
    #pragma unroll
    for (int o = 16; o > 0; o >>= 1) v += __shfl_down_sync(0xffffffff, v, o);
    if ((tid & 31) == 0) sh[tid >> 5] = v;
    __syncthreads();
    if (tid < 32) {
        v = (tid < (int)(blockDim.x >> 5)) ? sh[tid] : 0.0f;
        #pragma unroll
        for (int o = 16; o > 0; o >>= 1) v += __shfl_down_sync(0xffffffff, v, o);
        if (tid == 0) sh[0] = v;
    }
    __syncthreads();
    return sh[0];
}

// ---------------- fused adj pass: rowsum+1 -> denom, colsum (atomic), fp16 split ----
__global__ void __launch_bounds__(256)
adj_pass_kernel(const float* __restrict__ adj, float* __restrict__ denom,
                float* __restrict__ colsum, __half* __restrict__ Ah,
                __half* __restrict__ Al) {
    __shared__ float rowacc[128];
    const int b = blockIdx.y;
    const int r0 = blockIdx.x * 128;
    const int tid = threadIdx.x;
    const int lane = tid & 31;
    const int col0 = tid * 4;

    for (int i = tid; i < 128; i += 256) rowacc[i] = 0.0f;
    __syncthreads();

    const float* src = adj + (size_t)b * NN * NN + (size_t)r0 * NN;
    __half* dh = Ah + (size_t)b * NN * NN + (size_t)r0 * NN;
    __half* dl = Al + (size_t)b * NN * NN + (size_t)r0 * NN;

    float cs0 = 0.f, cs1 = 0.f, cs2 = 0.f, cs3 = 0.f;

    for (int r = 0; r < 128; r++) {
        float4 v = *reinterpret_cast<const float4*>(&src[(size_t)r * NN + col0]);
        __half h0 = __float2half_rn(v.x), h1 = __float2half_rn(v.y);
        __half h2 = __float2half_rn(v.z), h3 = __float2half_rn(v.w);
        __half l0 = __float2half_rn(v.x - __half2float(h0));
        __half l1 = __float2half_rn(v.y - __half2float(h1));
        __half l2 = __float2half_rn(v.z - __half2float(h2));
        __half l3 = __float2half_rn(v.w - __half2float(h3));
        *reinterpret_cast<__half2*>(&dh[(size_t)r * NN + col0])     = __halves2half2(h0, h1);
        *reinterpret_cast<__half2*>(&dh[(size_t)r * NN + col0 + 2]) = __halves2half2(h2, h3);
        *reinterpret_cast<__half2*>(&dl[(size_t)r * NN + col0])     = __halves2half2(l0, l1);
        *reinterpret_cast<__half2*>(&dl[(size_t)r * NN + col0 + 2]) = __halves2half2(l2, l3);
        cs0 += v.x; cs1 += v.y; cs2 += v.z; cs3 += v.w;
        float s = (v.x + v.y) + (v.z + v.w);
        #pragma unroll
        for (int o = 16; o > 0; o >>= 1) s += __shfl_down_sync(0xffffffff, s, o);
        if (lane == 0) atomicAdd(&rowacc[r], s);
    }
    __syncthreads();
    if (tid < 128) denom[(size_t)b * NN + r0 + tid] = rowacc[tid] + 1.0f;
    float* cdst = colsum + (size_t)b * NN + col0;
    atomicAdd(cdst + 0, cs0);
    atomicAdd(cdst + 1, cs1);
    atomicAdd(cdst + 2, cs2);
    atomicAdd(cdst + 3, cs3);
}

__global__ void zero_kernel(float* __restrict__ p, int n) {
    int i = blockIdx.x * blockDim.x + threadIdx.x;
    if (i < n) p[i] = 0.0f;
}

__global__ void split_kernel(const float* __restrict__ src, __half* __restrict__ h,
                             __half* __restrict__ l, int n4) {
    int i = blockIdx.x * blockDim.x + threadIdx.x;
    if (i >= n4) return;
    float4 v = reinterpret_cast<const float4*>(src)[i];
    __half h0 = __float2half_rn(v.x), h1 = __float2half_rn(v.y);
    __half h2 = __float2half_rn(v.z), h3 = __float2half_rn(v.w);
    __half l0 = __float2half_rn(v.x - __half2float(h0));
    __half l1 = __float2half_rn(v.y - __half2float(h1));
    __half l2 = __float2half_rn(v.z - __half2float(h2));
    __half l3 = __float2half_rn(v.w - __half2float(h3));
    reinterpret_cast<__half2*>(h)[i * 2 + 0] = __halves2half2(h0, h1);
    reinterpret_cast<__half2*>(h)[i * 2 + 1] = __halves2half2(h2, h3);
    reinterpret_cast<__half2*>(l)[i * 2 + 0] = __halves2half2(l0, l1);
    reinterpret_cast<__half2*>(l)[i * 2 + 1] = __halves2half2(l2, l3);
}

__global__ void transpose_split(const float* __restrict__ x, __half* __restrict__ th,
                                __half* __restrict__ tl) {
    __shared__ float tile[32][33];
    int b = blockIdx.z;
    int m0 = blockIdx.y * 32, d0 = blockIdx.x * 32;
    const float* src = x + (size_t)b * NN * DD;
    int tx = threadIdx.x, ty = threadIdx.y;
    #pragma unroll
    for (int j = 0; j < 32; j += 8)
        tile[ty + j][tx] = src[(size_t)(m0 + ty + j) * DD + d0 + tx];
    __syncthreads();
    __half* dh = th + (size_t)b * DD * NN;
    __half* dl = tl + (size_t)b * DD * NN;
    #pragma unroll
    for (int j = 0; j < 32; j += 8) {
        float v = tile[tx][ty + j];
        __half h = __float2half_rn(v);
        __half l = __float2half_rn(v - __half2float(h));
        dh[(size_t)(d0 + ty + j) * NN + m0 + tx] = h;
        dl[(size_t)(d0 + ty + j) * NN + m0 + tx] = l;
    }
}

// ---------------- HMMA GEMM: CTA tile 128x64, warp tile 32x32, 2 CTAs/SM ------
// D = Ah@Bh^T (fp32 acc) + [Ah@Bl^T + Al@Bh^T] (shared fp16 acc, 2x rate).
#define KT 64
#define A_TB 16384                        // 128 rows x 128 B
#define B_TB 8192                         // 64 rows x 128 B
#define STAGE_BYTES (2 * A_TB + 2 * B_TB) // 48 KB
#define GEMM_SMEM (2 * STAGE_BYTES)       // 96 KB -> 2 CTAs/SM

template <int KTOT, int EPI>
__global__ void __launch_bounds__(256, 2)
gemm_hmma(const __half* __restrict__ Ah, const __half* __restrict__ Al,
          const __half* __restrict__ Bh, const __half* __restrict__ Bl,
          const float* __restrict__ Xadd, __half* __restrict__ OutH, __half* __restrict__ OutL,
          const float* __restrict__ bias, const float* __restrict__ denom,
          float* __restrict__ OutF) {
    extern __shared__ char smem[];
    const uint32_t sb = smem_u32(smem);
    const int tid = threadIdx.x;
    const int wid = tid >> 5;
    const int lane = tid & 31;

    long aRow0, bRow0, outRow0;
    if (EPI == 1) {
        int b = blockIdx.z;
        aRow0 = (long)b * NN + blockIdx.y * 128;
        bRow0 = (long)b * DD + blockIdx.x * 64;
        outRow0 = aRow0;
    } else {
        aRow0 = (long)blockIdx.y * 128;
        bRow0 = (long)blockIdx.x * 64;
        outRow0 = aRow0;
    }
    const int colBlk = blockIdx.x * 64;

    const __half* srcA_h = Ah + aRow0 * KTOT;
    const __half* srcA_l = Al + aRow0 * KTOT;
    const __half* srcB_h = Bh + bRow0 * KTOT;
    const __half* srcB_l = Bl + bRow0 * KTOT;

    const int m0 = (wid & 3) * 32;    // 0..96
    const int n0 = (wid >> 2) * 32;   // 0 / 32

    const int ltile = lane >> 3;
    const int rowInTile = (lane & 7) + ((ltile & 1) << 3);
    const int kk = ltile >> 1;
    const int lx = lane & 7;

    float acc[2][4][4];                 // main term, fp32
    uint32_t cacc[2][4][2];             // cross terms, fp16 (half2 x2)
    #pragma unroll
    for (int a = 0; a < 2; a++)
        #pragma unroll
        for (int b2 = 0; b2 < 4; b2++) {
            #pragma unroll
            for (int c = 0; c < 4; c++) acc[a][b2][c] = 0.0f;
            cacc[a][b2][0] = 0u; cacc[a][b2][1] = 0u;
        }

    const int nk = KTOT / KT;

    auto issue = [&](int i) {
        const uint32_t stg = sb + (uint32_t)(i & 1) * STAGE_BYTES;
        const int k0 = i * KT;
        // A tiles: 128 rows each -> 1024 chunks -> 4 per thread
        #pragma unroll
        for (int t = 0; t < 2; t++) {
            const __half* base = (t == 0) ? srcA_h : srcA_l;
            #pragma unroll
            for (int jj = 0; jj < 4; jj++) {
                int cid = tid + jj * 256;
                int row = cid >> 3, c = cid & 7;
                cp_async16(stg + t * A_TB + row * 128 + ((c ^ (row & 7)) << 4),
                           base + (size_t)row * KTOT + k0 + c * 8);
            }
        }
        // B tiles: 64 rows each -> 512 chunks -> 2 per thread
        #pragma unroll
        for (int t = 0; t < 2; t++) {
            const __half* base = (t == 0) ? srcB_h : srcB_l;
            #pragma unroll
            for (int jj = 0; jj < 2; jj++) {
                int cid = tid + jj * 256;
                int row = cid >> 3, c = cid & 7;
                cp_async16(stg + 2 * A_TB + t * B_TB + row * 128 + ((c ^ (row & 7)) << 4),
                           base + (size_t)row * KTOT + k0 + c * 8);
            }
        }
        cp_commit();
    };

    issue(0);

    for (int i = 0; i < nk; i++) {
        if (i + 1 < nk) issue(i + 1);
        if (i + 1 < nk) cp_wait<1>(); else cp_wait<0>();
        __syncthreads();

        const uint32_t stg = sb + (uint32_t)(i & 1) * STAGE_BYTES;
        const uint32_t sAh = stg, sAl = stg + A_TB;
        const uint32_t sBh = stg + 2 * A_TB, sBl = stg + 2 * A_TB + B_TB;

        #pragma unroll
        for (int ks = 0; ks < 4; ks++) {
            const uint32_t swz = (uint32_t)(((ks * 2 + kk) ^ lx) << 4);
            uint32_t af[2][4], bh[4][2], bl[4][2];
            // A-hi fragments
            #pragma unroll
            for (int mf = 0; mf < 2; mf++) {
                uint32_t off = (uint32_t)((m0 + mf * 16 + rowInTile) * 128) + swz;
                ldsm4(af[mf], sAh + off);
            }
            // B fragments (both hi and lo, 32 cols)
            #pragma unroll
            for (int nh = 0; nh < 2; nh++) {
                uint32_t off = (uint32_t)((n0 + nh * 16 + rowInTile) * 128) + swz;
                uint32_t r[4], s[4];
                ldsm4(r, sBh + off);
                ldsm4(s, sBl + off);
                bh[nh * 2][0] = r[0]; bh[nh * 2][1] = r[2];
                bh[nh * 2 + 1][0] = r[1]; bh[nh * 2 + 1][1] = r[3];
                bl[nh * 2][0] = s[0]; bl[nh * 2][1] = s[2];
                bl[nh * 2 + 1][0] = s[1]; bl[nh * 2 + 1][1] = s[3];
            }
            // main: fp32 acc
            #pragma unroll
            for (int mf = 0; mf < 2; mf++)
                #pragma unroll
                for (int nf = 0; nf < 4; nf++)
                    mma16816(acc[mf][nf], af[mf], bh[nf]);
            // cross 1: Ah x Bl, fp16 acc
            #pragma unroll
            for (int mf = 0; mf < 2; mf++)
                #pragma unroll
                for (int nf = 0; nf < 4; nf++)
                    mma16816h(cacc[mf][nf], af[mf], bl[nf]);
            // A-lo fragments (overwrite)
            #pragma unroll
            for (int mf = 0; mf < 2; mf++) {
                uint32_t off = (uint32_t)((m0 + mf * 16 + rowInTile) * 128) + swz;
                ldsm4(af[mf], sAl + off);
            }
            // cross 2: Al x Bh, fp16 acc (same accumulator)
            #pragma unroll
            for (int mf = 0; mf < 2; mf++)
                #pragma unroll
                for (int nf = 0; nf < 4; nf++)
                    mma16816h(cacc[mf][nf], af[mf], bh[nf]);
        }
        __syncthreads();
    }

    // ---- epilogue ----
    const int rr = lane >> 2;
    const int cc = (lane & 3) * 2;
    #pragma unroll
    for (int mf = 0; mf < 2; mf++) {
        #pragma unroll
        for (int hf = 0; hf < 2; hf++) {
            long grow = outRow0 + m0 + mf * 16 + rr + hf * 8;
            float invd = (EPI == 2) ? (1.0f / denom[grow]) : 0.0f;
            #pragma unroll
            for (int nf = 0; nf < 4; nf++) {
                int gcol = colBlk + n0 + nf * 8 + cc;
                size_t gi = (size_t)grow * DD + gcol;
                __half2 cr = *reinterpret_cast<__half2*>(&cacc[mf][nf][hf]);
                float v0 = acc[mf][nf][hf * 2 + 0] + __low2float(cr);
                float v1 = acc[mf][nf][hf * 2 + 1] + __high2float(cr);
                if (EPI == 1) {
                    float2 xv = *reinterpret_cast<const float2*>(&Xadd[gi]);
                    v0 += xv.x; v1 += xv.y;
                    __half h0 = __float2half_rn(v0), h1 = __float2half_rn(v1);
                    __half l0 = __float2half_rn(v0 - __half2float(h0));
                    __half l1 = __float2half_rn(v1 - __half2float(h1));
                    *reinterpret_cast<__half2*>(&OutH[gi]) = __halves2half2(h0, h1);
                    *reinterpret_cast<__half2*>(&OutL[gi]) = __halves2half2(l0, l1);
                } else {
                    float2 bv = *reinterpret_cast<const float2*>(&bias[gcol]);
                    float2 o;
                    o.x = fmaxf((v0 + 2.0f * bv.x) * invd, 0.0f);
                    o.y = fmaxf((v1 + 2.0f * bv.y) * invd, 0.0f);
                    *reinterpret_cast<float2*>(&OutF[gi]) = o;
                }
            }
        }
    }
}

// ---------------- LayerNorm ----------------
__global__ void ln_kernel(const float* __restrict__ X, const float* __restrict__ g,
                          const float* __restrict__ b, float* __restrict__ out) {
    __shared__ float sh[32];
    const int row = blockIdx.x;
    const float* p = X + (size_t)row * DD;
    const int tid = threadIdx.x;
    float v0 = p[tid];
    float v1 = p[tid + 256];
    float mu = block_reduce_sum(v0 + v1, sh) * (1.0f / DD);
    float d0 = v0 - mu, d1 = v1 - mu;
    float var = block_reduce_sum(d0 * d0 + d1 * d1, sh) * (1.0f / DD);
    float r = rsqrtf(var + LN_EPS);
    out[(size_t)row * DD + tid] = d0 * r * g[tid] + b[tid];
    out[(size_t)row * DD + tid + 256] = d1 * r * g[tid + 256] + b[tid + 256];
}

__global__ void mask_kernel(const float* __restrict__ denom, const float* __restrict__ colsum,
                            float* __restrict__ out, int count) {
    int i = blockIdx.x * blockDim.x + threadIdx.x;
    if (i >= count) return;
    if (i < BB * NN) {
        float rs = denom[i] - 1.0f;
        out[i] = ((rs + colsum[i]) == 0.0f) ? 1.0f : 0.0f;
    } else {
        out[i] = 0.0f;
    }
}

// ---------------- launch ----------------
extern "C" void kernel_launch(void* const* d_in, const int* in_sizes, int n_in,
                              void* d_out, int out_size) {
    const float* adj = (const float*)d_in[0];
    const float* emb = (const float*)d_in[1];
    const float* W0w = (const float*)d_in[3];
    const float* W0b = (const float*)d_in[4];
    const float* W1w = (const float*)d_in[5];
    const float* W1b = (const float*)d_in[6];
    const float* lng = (const float*)d_in[7];
    const float* lnb = (const float*)d_in[8];
    float* out = (float*)d_out;

    float *denom, *colsum, *x;
    __half *adjh, *adjl, *xth, *xtl, *yh, *yl, *w0h, *w0l, *w1h, *w1l;
    cudaGetSymbolAddress((void**)&denom, g_denom);
    cudaGetSymbolAddress((void**)&colsum, g_colsum);
    cudaGetSymbolAddress((void**)&x, g_x);
    cudaGetSymbolAddress((void**)&adjh, g_adj_h);
    cudaGetSymbolAddress((void**)&adjl, g_adj_l);
    cudaGetSymbolAddress((void**)&xth, g_xT_h);
    cudaGetSymbolAddress((void**)&xtl, g_xT_l);
    cudaGetSymbolAddress((void**)&yh, g_y_h);
    cudaGetSymbolAddress((void**)&yl, g_y_l);
    cudaGetSymbolAddress((void**)&w0h, g_W0_h);
    cudaGetSymbolAddress((void**)&w0l, g_W0_l);
    cudaGetSymbolAddress((void**)&w1h, g_W1_h);
    cudaGetSymbolAddress((void**)&w1l, g_W1_l);

    cudaFuncSetAttribute(gemm_hmma<1024, 1>, cudaFuncAttributeMaxDynamicSharedMemorySize, GEMM_SMEM);
    cudaFuncSetAttribute(gemm_hmma<512, 2>, cudaFuncAttributeMaxDynamicSharedMemorySize, GEMM_SMEM);

    dim3 tg(DD / 32, NN / 32, BB);
    dim3 tb(32, 8);
    dim3 ga(8, BB);
    dim3 g1(DD / 64, NN / 128, BB);         // (8, 8, 32)
    dim3 g2(DD / 64, (BB * NN) / 128, 1);   // (8, 256)
    int w4 = (DD * DD) / 4;

    zero_kernel<<<(BB * NN + 255) / 256, 256>>>(colsum, BB * NN);              // 1
    adj_pass_kernel<<<ga, 256>>>(adj, denom, colsum, adjh, adjl);              // 2
    transpose_split<<<tg, tb>>>(emb, xth, xtl);                                // 3
    gemm_hmma<1024, 1><<<g1, 256, GEMM_SMEM>>>(adjh, adjl, xth, xtl, emb, yh, yl,
                                               nullptr, nullptr, nullptr);     // 4
    split_kernel<<<(w4 + 255) / 256, 256>>>(W0w, w0h, w0l, w4);                // 5
    gemm_hmma<512, 2><<<g2, 256, GEMM_SMEM>>>(yh, yl, w0h, w0l, nullptr, nullptr, nullptr,
                                              W0b, denom, x);                  // 6
    split_kernel<<<(w4 + 255) / 256, 256>>>(W1w, w1h, w1l, w4);                // 7
    transpose_split<<<tg, tb>>>(x, xth, xtl);                                  // 8
    gemm_hmma<1024, 1><<<g1, 256, GEMM_SMEM>>>(adjh, adjl, xth, xtl, x, yh, yl,
                                               nullptr, nullptr, nullptr);     // 9
    gemm_hmma<512, 2><<<g2, 256, GEMM_SMEM>>>(yh, yl, w1h, w1l, nullptr, nullptr, nullptr,
                                              W1b, denom, x);                  // 10

    ln_kernel<<<BB * NN, 256>>>(x, lng, lnb, out);                             // 11

    int extra = out_size - BB * NN * DD;
    if (extra > 0) {
        mask_kernel<<<(extra + 255) / 256, 256>>>(denom, colsum,
                                                  out + (size_t)BB * NN * DD, extra);
    }
}